// round 7
// baseline (speedup 1.0000x reference)
#include <cuda_runtime.h>

#define DD 512
#define BB 512
#define KT 16

__device__ float g_x[BB * DD];

__constant__ float INVFACT[KT] = {
    1.0f, 1.0f, 0.5f,
    1.6666666666666666e-1f, 4.1666666666666664e-2f, 8.3333333333333333e-3f,
    1.3888888888888889e-3f, 1.9841269841269841e-4f, 2.4801587301587302e-5f,
    2.7557319223985893e-6f, 2.7557319223985888e-7f, 2.5052108385441720e-8f,
    2.0876756987868100e-9f, 1.6059043836821613e-10f, 1.1470745597729725e-11f,
    7.6471637318198160e-13f
};

typedef unsigned long long ull;

__device__ __forceinline__ ull pk2(float lo, float hi) {
    ull r; asm("mov.b64 %0, {%1,%2};" : "=l"(r) : "f"(lo), "f"(hi)); return r;
}
__device__ __forceinline__ void upk2(ull v, float& lo, float& hi) {
    asm("mov.b64 {%0,%1}, %2;" : "=f"(lo), "=f"(hi) : "l"(v));
}
__device__ __forceinline__ ull fma2(ull a, ull b, ull c) {
    ull d; asm("fma.rn.f32x2 %0, %1, %2, %3;" : "=l"(d) : "l"(a), "l"(b), "l"(c));
    return d;
}
__device__ __forceinline__ ull add2(ull a, ull b) {
    ull d; asm("add.rn.f32x2 %0, %1, %2;" : "=l"(d) : "l"(a), "l"(b)); return d;
}
__device__ __forceinline__ ull mul2(ull a, ull b) {
    ull d; asm("mul.rn.f32x2 %0, %1, %2;" : "=l"(d) : "l"(a), "l"(b)); return d;
}

// ---------------------------------------------------------------------------
// Kernel 1: g_x = tanh(img @ W^T + b).
// 32x32 tile, BK=32, 128 thr, grid 256 (~2 CTAs/SM -> 2 warps/SMSP).
// R3-proven single-buffer structure: store -> sync -> prefetch -> compute -> sync.
// Thread = 1 M-pair x 4 N via f32x2.
// ---------------------------------------------------------------------------
__global__ __launch_bounds__(128) void gemm_tanh_kernel(
    const float* __restrict__ A,
    const float* __restrict__ W,
    const float* __restrict__ bias)
{
    __shared__ __align__(16) float Asm[32][36];
    __shared__ __align__(16) float Bsm[32][36];

    const int t  = threadIdx.x;
    const int tx = t & 7;          // 4 N cols
    const int ty = t >> 3;         // M-pair (rows 2ty, 2ty+1)
    const int rowBase = blockIdx.y * 32;
    const int colBase = blockIdx.x * 32;

    const int lr = t >> 2;         // load row 0..31
    const int lk = (t & 3) * 8;    // load k-offset {0,8,16,24}

    ull acc[4] = {0ull, 0ull, 0ull, 0ull};

    float4 pfA0, pfA1, pfB0, pfB1;
    pfA0 = *(const float4*)&A[(rowBase + lr) * DD + lk];
    pfA1 = *(const float4*)&A[(rowBase + lr) * DD + lk + 4];
    pfB0 = *(const float4*)&W[(colBase + lr) * DD + lk];
    pfB1 = *(const float4*)&W[(colBase + lr) * DD + lk + 4];

    for (int tile = 0; tile < 16; tile++) {
        Asm[lk+0][lr] = pfA0.x; Asm[lk+1][lr] = pfA0.y;
        Asm[lk+2][lr] = pfA0.z; Asm[lk+3][lr] = pfA0.w;
        Asm[lk+4][lr] = pfA1.x; Asm[lk+5][lr] = pfA1.y;
        Asm[lk+6][lr] = pfA1.z; Asm[lk+7][lr] = pfA1.w;
        Bsm[lk+0][lr] = pfB0.x; Bsm[lk+1][lr] = pfB0.y;
        Bsm[lk+2][lr] = pfB0.z; Bsm[lk+3][lr] = pfB0.w;
        Bsm[lk+4][lr] = pfB1.x; Bsm[lk+5][lr] = pfB1.y;
        Bsm[lk+6][lr] = pfB1.z; Bsm[lk+7][lr] = pfB1.w;
        __syncthreads();

        if (tile < 15) {
            const int kc = (tile + 1) * 32;
            pfA0 = *(const float4*)&A[(rowBase + lr) * DD + kc + lk];
            pfA1 = *(const float4*)&A[(rowBase + lr) * DD + kc + lk + 4];
            pfB0 = *(const float4*)&W[(colBase + lr) * DD + kc + lk];
            pfB1 = *(const float4*)&W[(colBase + lr) * DD + kc + lk + 4];
        }

        #pragma unroll
        for (int kk = 0; kk < 32; kk++) {
            ull aa = *(const ull*)&Asm[kk][ty * 2];
            float4 bv = *(const float4*)&Bsm[kk][tx * 4];
            acc[0] = fma2(aa, pk2(bv.x, bv.x), acc[0]);
            acc[1] = fma2(aa, pk2(bv.y, bv.y), acc[1]);
            acc[2] = fma2(aa, pk2(bv.z, bv.z), acc[2]);
            acc[3] = fma2(aa, pk2(bv.w, bv.w), acc[3]);
        }
        __syncthreads();
    }

    float4 bl = *(const float4*)&bias[colBase + tx * 4];
    float lo0, hi0, lo1, hi1, lo2, hi2, lo3, hi3;
    upk2(acc[0], lo0, hi0); upk2(acc[1], lo1, hi1);
    upk2(acc[2], lo2, hi2); upk2(acc[3], lo3, hi3);
    float4 o0, o1;
    o0.x = tanhf(lo0 + bl.x); o0.y = tanhf(lo1 + bl.y);
    o0.z = tanhf(lo2 + bl.z); o0.w = tanhf(lo3 + bl.w);
    o1.x = tanhf(hi0 + bl.x); o1.y = tanhf(hi1 + bl.y);
    o1.z = tanhf(hi2 + bl.z); o1.w = tanhf(hi3 + bl.w);
    const int r0 = rowBase + ty * 2;
    *(float4*)&g_x[r0 * DD + colBase + tx * 4]       = o0;
    *(float4*)&g_x[(r0 + 1) * DD + colBase + tx * 4] = o1;
}

// ---------------------------------------------------------------------------
// Kernel 2: co-attention, separable Taylor series, f32x2, KT=16.
// ONE batch row per block, 128 thr (4 warps, each owns a 128-elem quarter).
// Grid 512 -> ~3.5 blocks/SM, all 148 SMs busy.
// ---------------------------------------------------------------------------
__global__ __launch_bounds__(128, 1) void coatten_kernel(
    const float* __restrict__ img,
    const float* __restrict__ audio,
    float* __restrict__ out)
{
    const int wid  = threadIdx.x >> 5;   // quarter 0..3
    const int lane = threadIdx.x & 31;
    const int b    = blockIdx.x;
    const int base = wid * 128;

    __shared__ float redA[4][32];
    __shared__ float redB[4][32];

    const float* xrow = g_x   + b * DD;
    const float* arow = audio + b * DD;
    const float* irow = img   + b * DD;
    float* orow = out + (size_t)b * (4 * DD);

    const int idx = base + 4 * lane;
    ull x2[2], a2[2];
    {
        ulonglong2 xv = *(const ulonglong2*)&xrow[idx];
        ulonglong2 av = *(const ulonglong2*)&arow[idx];
        x2[0] = xv.x; x2[1] = xv.y;
        a2[0] = av.x; a2[1] = av.y;
        *(ulonglong2*)&orow[idx]      = *(const ulonglong2*)&irow[idx];
        *(ulonglong2*)&orow[DD + idx] = av;
    }

    const ull ONE2 = 0x3F8000003F800000ull;

    // ===== phase A: partial m_k = sum x^k, p_k = sum a^k (this quarter) =====
    float mc[KT], pc[KT];
    {
        ull svx[2] = {ONE2, ONE2}, sva[2] = {ONE2, ONE2};
        #pragma unroll
        for (int ch = 0; ch < 2; ch++) {
            ull mA[8], pA[8];
            #pragma unroll
            for (int k = 0; k < 8; k++) { mA[k] = 0ull; pA[k] = 0ull; }
            #pragma unroll
            for (int q = 0; q < 2; q++) {
                ull pwx = svx[q], pwa = sva[q];
                #pragma unroll
                for (int k = 0; k < 8; k++) {
                    mA[k] = add2(mA[k], pwx); pwx = mul2(pwx, x2[q]);
                    pA[k] = add2(pA[k], pwa); pwa = mul2(pwa, a2[q]);
                }
                svx[q] = pwx; sva[q] = pwa;
            }
            #pragma unroll
            for (int k = 0; k < 8; k++) {
                float lo, hi;
                upk2(mA[k], lo, hi); mc[ch*8+k] = lo + hi;
                upk2(pA[k], lo, hi); pc[ch*8+k] = lo + hi;
            }
        }
    }
    #pragma unroll
    for (int off = 16; off > 0; off >>= 1)
        #pragma unroll
        for (int k = 0; k < KT; k++) {
            mc[k] += __shfl_xor_sync(0xffffffffu, mc[k], off);
            pc[k] += __shfl_xor_sync(0xffffffffu, pc[k], off);
        }
    if (lane == 0) {
        #pragma unroll
        for (int k = 0; k < KT; k++) {
            redA[wid][k]      = mc[k];
            redA[wid][KT + k] = pc[k];
        }
    }
    __syncthreads();
    #pragma unroll
    for (int k = 0; k < KT; k++) {
        mc[k] = (redA[0][k] + redA[1][k] + redA[2][k] + redA[3][k]) * INVFACT[k];
        pc[k] = (redA[0][KT+k] + redA[1][KT+k] + redA[2][KT+k] + redA[3][KT+k]) * INVFACT[k];
    }

    // Horner: c_j = eval(mc at a_j), r_i = eval(pc at x_i) -> w1, w2
    ull w1[2], w2[2];
    {
        ull sc[2], sr[2];
        ull tm = pk2(mc[KT-1], mc[KT-1]), tp = pk2(pc[KT-1], pc[KT-1]);
        sc[0] = tm; sc[1] = tm; sr[0] = tp; sr[1] = tp;
        #pragma unroll
        for (int k = KT - 2; k >= 0; k--) {
            ull cm = pk2(mc[k], mc[k]), cp = pk2(pc[k], pc[k]);
            #pragma unroll
            for (int q = 0; q < 2; q++) {
                sc[q] = fma2(sc[q], a2[q], cm);
                sr[q] = fma2(sr[q], x2[q], cp);
            }
        }
        #pragma unroll
        for (int q = 0; q < 2; q++) {
            float clo, chi, rlo, rhi, alo, ahi, xlo, xhi;
            upk2(sc[q], clo, chi); upk2(a2[q], alo, ahi);
            upk2(sr[q], rlo, rhi); upk2(x2[q], xlo, xhi);
            w1[q] = pk2(__fdividef(alo, clo), __fdividef(ahi, chi));
            w2[q] = pk2(__fdividef(xlo, rlo), __fdividef(xhi, rhi));
        }
    }

    // ===== phase B: u_k = sum w1 a^k, v_k = sum w2 x^k (this quarter) =====
    float uc[KT], vc[KT];
    {
        ull svu[2] = {w1[0], w1[1]}, svv[2] = {w2[0], w2[1]};
        #pragma unroll
        for (int ch = 0; ch < 2; ch++) {
            ull uA[8], vA[8];
            #pragma unroll
            for (int k = 0; k < 8; k++) { uA[k] = 0ull; vA[k] = 0ull; }
            #pragma unroll
            for (int q = 0; q < 2; q++) {
                ull pwu = svu[q], pwv = svv[q];
                #pragma unroll
                for (int k = 0; k < 8; k++) {
                    uA[k] = add2(uA[k], pwu); pwu = mul2(pwu, a2[q]);
                    vA[k] = add2(vA[k], pwv); pwv = mul2(pwv, x2[q]);
                }
                svu[q] = pwu; svv[q] = pwv;
            }
            #pragma unroll
            for (int k = 0; k < 8; k++) {
                float lo, hi;
                upk2(uA[k], lo, hi); uc[ch*8+k] = lo + hi;
                upk2(vA[k], lo, hi); vc[ch*8+k] = lo + hi;
            }
        }
    }
    #pragma unroll
    for (int off = 16; off > 0; off >>= 1)
        #pragma unroll
        for (int k = 0; k < KT; k++) {
            uc[k] += __shfl_xor_sync(0xffffffffu, uc[k], off);
            vc[k] += __shfl_xor_sync(0xffffffffu, vc[k], off);
        }
    if (lane == 0) {
        #pragma unroll
        for (int k = 0; k < KT; k++) {
            redB[wid][k]      = uc[k];
            redB[wid][KT + k] = vc[k];
        }
    }
    __syncthreads();
    #pragma unroll
    for (int k = 0; k < KT; k++) {
        uc[k] = (redB[0][k] + redB[1][k] + redB[2][k] + redB[3][k]) * INVFACT[k];
        vc[k] = (redB[0][KT+k] + redB[1][KT+k] + redB[2][KT+k] + redB[3][KT+k]) * INVFACT[k];
    }

    // Horner: C_img = eval(uc at x), C_audio = eval(vc at a); store
    {
        ull si[2], so[2];
        ull tu = pk2(uc[KT-1], uc[KT-1]), tv = pk2(vc[KT-1], vc[KT-1]);
        si[0] = tu; si[1] = tu; so[0] = tv; so[1] = tv;
        #pragma unroll
        for (int k = KT - 2; k >= 0; k--) {
            ull cu = pk2(uc[k], uc[k]), cv = pk2(vc[k], vc[k]);
            #pragma unroll
            for (int q = 0; q < 2; q++) {
                si[q] = fma2(si[q], x2[q], cu);
                so[q] = fma2(so[q], a2[q], cv);
            }
        }
        ulonglong2 vi; vi.x = si[0]; vi.y = si[1];
        ulonglong2 vo; vo.x = so[0]; vo.y = so[1];
        *(ulonglong2*)&orow[2 * DD + idx] = vi;
        *(ulonglong2*)&orow[3 * DD + idx] = vo;
    }
}

extern "C" void kernel_launch(void* const* d_in, const int* in_sizes, int n_in,
                              void* d_out, int out_size)
{
    const float* img   = (const float*)d_in[0];
    const float* audio = (const float*)d_in[1];
    const float* W     = (const float*)d_in[2];
    const float* bias  = (const float*)d_in[3];
    float* out = (float*)d_out;

    gemm_tanh_kernel<<<dim3(16, 16), 128>>>(img, W, bias);
    coatten_kernel<<<512, 128>>>(img, audio, out);
}

// round 8
// speedup vs baseline: 1.1722x; 1.1722x over previous
#include <cuda_runtime.h>

#define DD 512
#define BB 512
#define KT 14

// raw GEMM partials (two K-halves), summed + tanh'ed inside coatten
__device__ float g_part[2 * BB * DD];

// inverse factorials by butterfly SLOT: [0..13]=mc, [16..29]=pc, rest dead
__constant__ float INVFS[32] = {
    1.0f, 1.0f, 0.5f,
    1.6666666666666666e-1f, 4.1666666666666664e-2f, 8.3333333333333333e-3f,
    1.3888888888888889e-3f, 1.9841269841269841e-4f, 2.4801587301587302e-5f,
    2.7557319223985893e-6f, 2.7557319223985888e-7f, 2.5052108385441720e-8f,
    2.0876756987868100e-9f, 1.6059043836821613e-10f,
    0.0f, 0.0f,
    1.0f, 1.0f, 0.5f,
    1.6666666666666666e-1f, 4.1666666666666664e-2f, 8.3333333333333333e-3f,
    1.3888888888888889e-3f, 1.9841269841269841e-4f, 2.4801587301587302e-5f,
    2.7557319223985893e-6f, 2.7557319223985888e-7f, 2.5052108385441720e-8f,
    2.0876756987868100e-9f, 1.6059043836821613e-10f,
    0.0f, 0.0f
};

typedef unsigned long long ull;

__device__ __forceinline__ ull pk2(float lo, float hi) {
    ull r; asm("mov.b64 %0, {%1,%2};" : "=l"(r) : "f"(lo), "f"(hi)); return r;
}
__device__ __forceinline__ void upk2(ull v, float& lo, float& hi) {
    asm("mov.b64 {%0,%1}, %2;" : "=f"(lo), "=f"(hi) : "l"(v));
}
__device__ __forceinline__ ull fma2(ull a, ull b, ull c) {
    ull d; asm("fma.rn.f32x2 %0, %1, %2, %3;" : "=l"(d) : "l"(a), "l"(b), "l"(c));
    return d;
}
__device__ __forceinline__ ull add2(ull a, ull b) {
    ull d; asm("add.rn.f32x2 %0, %1, %2;" : "=l"(d) : "l"(a), "l"(b)); return d;
}
__device__ __forceinline__ ull mul2(ull a, ull b) {
    ull d; asm("mul.rn.f32x2 %0, %1, %2;" : "=l"(d) : "l"(a), "l"(b)); return d;
}

// ---------------------------------------------------------------------------
// Kernel 1: g_part[h] = img @ W^T over K-half h. 32(M)x64(N) tile, BK=32,
// 8 k-tiles per CTA, grid (8,16,2)=256 CTAs, 128 thr.
// B stored pre-duplicated (b,b) in smem -> inner kk = 3 LDS + 8 fma2.
// ---------------------------------------------------------------------------
__global__ __launch_bounds__(128) void gemm_part_kernel(
    const float* __restrict__ A,
    const float* __restrict__ W)
{
    __shared__ __align__(16) float Asm[32][36];
    __shared__ __align__(16) ull  Bsm2[32][66];   // duplicated pairs, padded

    const int t  = threadIdx.x;
    const int ty = t & 7;          // m-group: rows 4ty..4ty+3
    const int tx = t >> 3;         // n-group: cols 4tx..4tx+3
    const int rowBase = blockIdx.y * 32;
    const int colBase = blockIdx.x * 64;
    const int kBase   = blockIdx.z * 256;

    const int lr  = t >> 2;        // A loader: row 0..31
    const int lk  = (t & 3) * 8;   // A loader: k {0,8,16,24}
    const int lrB = t >> 1;        // B loader: row 0..63
    const int lkB = (t & 1) * 16;  // B loader: k {0,16}

    ull acc[2][4];
    #pragma unroll
    for (int p = 0; p < 2; p++)
        #pragma unroll
        for (int n = 0; n < 4; n++) acc[p][n] = 0ull;

    float4 pa0, pa1, pb0, pb1, pb2, pb3;
    {
        const float* ap = &A[(rowBase + lr) * DD + kBase + lk];
        pa0 = *(const float4*)ap; pa1 = *(const float4*)(ap + 4);
        const float* bp = &W[(colBase + lrB) * DD + kBase + lkB];
        pb0 = *(const float4*)bp;      pb1 = *(const float4*)(bp + 4);
        pb2 = *(const float4*)(bp + 8); pb3 = *(const float4*)(bp + 12);
    }

    for (int tile = 0; tile < 8; tile++) {
        Asm[lk+0][lr] = pa0.x; Asm[lk+1][lr] = pa0.y;
        Asm[lk+2][lr] = pa0.z; Asm[lk+3][lr] = pa0.w;
        Asm[lk+4][lr] = pa1.x; Asm[lk+5][lr] = pa1.y;
        Asm[lk+6][lr] = pa1.z; Asm[lk+7][lr] = pa1.w;
        Bsm2[lkB+ 0][lrB] = pk2(pb0.x, pb0.x); Bsm2[lkB+ 1][lrB] = pk2(pb0.y, pb0.y);
        Bsm2[lkB+ 2][lrB] = pk2(pb0.z, pb0.z); Bsm2[lkB+ 3][lrB] = pk2(pb0.w, pb0.w);
        Bsm2[lkB+ 4][lrB] = pk2(pb1.x, pb1.x); Bsm2[lkB+ 5][lrB] = pk2(pb1.y, pb1.y);
        Bsm2[lkB+ 6][lrB] = pk2(pb1.z, pb1.z); Bsm2[lkB+ 7][lrB] = pk2(pb1.w, pb1.w);
        Bsm2[lkB+ 8][lrB] = pk2(pb2.x, pb2.x); Bsm2[lkB+ 9][lrB] = pk2(pb2.y, pb2.y);
        Bsm2[lkB+10][lrB] = pk2(pb2.z, pb2.z); Bsm2[lkB+11][lrB] = pk2(pb2.w, pb2.w);
        Bsm2[lkB+12][lrB] = pk2(pb3.x, pb3.x); Bsm2[lkB+13][lrB] = pk2(pb3.y, pb3.y);
        Bsm2[lkB+14][lrB] = pk2(pb3.z, pb3.z); Bsm2[lkB+15][lrB] = pk2(pb3.w, pb3.w);
        __syncthreads();

        if (tile < 7) {
            const int kc = kBase + (tile + 1) * 32;
            const float* ap = &A[(rowBase + lr) * DD + kc + lk];
            pa0 = *(const float4*)ap; pa1 = *(const float4*)(ap + 4);
            const float* bp = &W[(colBase + lrB) * DD + kc + lkB];
            pb0 = *(const float4*)bp;      pb1 = *(const float4*)(bp + 4);
            pb2 = *(const float4*)(bp + 8); pb3 = *(const float4*)(bp + 12);
        }

        #pragma unroll
        for (int kk = 0; kk < 32; kk++) {
            ulonglong2 aa  = *(const ulonglong2*)&Asm[kk][ty * 4];
            ulonglong2 b01 = *(const ulonglong2*)&Bsm2[kk][tx * 4];
            ulonglong2 b23 = *(const ulonglong2*)&Bsm2[kk][tx * 4 + 2];
            acc[0][0] = fma2(aa.x, b01.x, acc[0][0]);
            acc[0][1] = fma2(aa.x, b01.y, acc[0][1]);
            acc[0][2] = fma2(aa.x, b23.x, acc[0][2]);
            acc[0][3] = fma2(aa.x, b23.y, acc[0][3]);
            acc[1][0] = fma2(aa.y, b01.x, acc[1][0]);
            acc[1][1] = fma2(aa.y, b01.y, acc[1][1]);
            acc[1][2] = fma2(aa.y, b23.x, acc[1][2]);
            acc[1][3] = fma2(aa.y, b23.y, acc[1][3]);
        }
        __syncthreads();
    }

    float* gp = g_part + (size_t)blockIdx.z * BB * DD;
    #pragma unroll
    for (int p = 0; p < 2; p++) {
        float lo[4], hi[4];
        #pragma unroll
        for (int n = 0; n < 4; n++) upk2(acc[p][n], lo[n], hi[n]);
        float4 o0, o1;
        o0.x = lo[0]; o0.y = lo[1]; o0.z = lo[2]; o0.w = lo[3];
        o1.x = hi[0]; o1.y = hi[1]; o1.z = hi[2]; o1.w = hi[3];
        const int r0 = rowBase + ty * 4 + 2 * p;
        *(float4*)&gp[r0 * DD + colBase + tx * 4]       = o0;
        *(float4*)&gp[(r0 + 1) * DD + colBase + tx * 4] = o1;
    }
}

// ---------------------------------------------------------------------------
// Kernel 2: co-attention. Fuses x = tanh(part0+part1+bias) on load.
// 1 row/block, 128 thr (4 warps x 128-elem quarter), grid 512.
// Reduction: vector-halving scatter-butterfly (31 shfl) -> lane L owns slot L
// -> smem 4-way combine -> broadcast. Slots: [0..13]=mc/uc, [16..29]=pc/vc.
// ---------------------------------------------------------------------------
__global__ __launch_bounds__(128, 1) void coatten_kernel(
    const float* __restrict__ img,
    const float* __restrict__ audio,
    const float* __restrict__ bias,
    float* __restrict__ out)
{
    const int wid  = threadIdx.x >> 5;
    const int lane = threadIdx.x & 31;
    const int b    = blockIdx.x;
    const int idx  = wid * 128 + 4 * lane;

    __shared__ float redS[4][33];
    __shared__ float coefA[32];
    __shared__ float coefB[32];

    const float* g0   = g_part + (size_t)b * DD;
    const float* g1   = g_part + (size_t)(BB + b) * DD;
    const float* arow = audio + (size_t)b * DD;
    const float* irow = img   + (size_t)b * DD;
    float* orow = out + (size_t)b * (4 * DD);

    ull x2[2], a2[2];
    {
        float4 p0 = *(const float4*)&g0[idx];
        float4 p1 = *(const float4*)&g1[idx];
        float4 bl = *(const float4*)&bias[idx];
        float xs0 = tanhf(p0.x + p1.x + bl.x);
        float xs1 = tanhf(p0.y + p1.y + bl.y);
        float xs2 = tanhf(p0.z + p1.z + bl.z);
        float xs3 = tanhf(p0.w + p1.w + bl.w);
        x2[0] = pk2(xs0, xs1); x2[1] = pk2(xs2, xs3);
        ulonglong2 av = *(const ulonglong2*)&arow[idx];
        a2[0] = av.x; a2[1] = av.y;
        *(ulonglong2*)&orow[idx]      = *(const ulonglong2*)&irow[idx];
        *(ulonglong2*)&orow[DD + idx] = av;
    }

    const ull ONE2 = 0x3F8000003F800000ull;
    float v[32];

    // ===== phase A: partial moments m_k = sum x^k, p_k = sum a^k =====
    {
        ull svx[2] = {ONE2, ONE2}, sva[2] = {ONE2, ONE2};
        #pragma unroll
        for (int ch = 0; ch < 2; ch++) {
            ull mA[7], pA[7];
            #pragma unroll
            for (int k = 0; k < 7; k++) { mA[k] = 0ull; pA[k] = 0ull; }
            #pragma unroll
            for (int q = 0; q < 2; q++) {
                ull pwx = svx[q], pwa = sva[q];
                #pragma unroll
                for (int k = 0; k < 7; k++) {
                    mA[k] = add2(mA[k], pwx); pwx = mul2(pwx, x2[q]);
                    pA[k] = add2(pA[k], pwa); pwa = mul2(pwa, a2[q]);
                }
                svx[q] = pwx; sva[q] = pwa;
            }
            #pragma unroll
            for (int k = 0; k < 7; k++) {
                float lo, hi;
                upk2(mA[k], lo, hi); v[ch * 7 + k]      = lo + hi;
                upk2(pA[k], lo, hi); v[16 + ch * 7 + k] = lo + hi;
            }
        }
        v[14] = 0.f; v[15] = 0.f; v[30] = 0.f; v[31] = 0.f;
    }
    // scatter-butterfly: lane L ends owning slot L in v[0]
    #pragma unroll
    for (int o = 16; o >= 1; o >>= 1) {
        const bool up = (lane & o);
        #pragma unroll
        for (int i = 0; i < o; i++) {
            float send = up ? v[i] : v[i + o];
            float got  = __shfl_xor_sync(0xffffffffu, send, o);
            v[i] = (up ? v[i + o] : v[i]) + got;
        }
    }
    redS[wid][lane] = v[0];
    __syncthreads();
    if (threadIdx.x < 32)
        coefA[threadIdx.x] = (redS[0][threadIdx.x] + redS[1][threadIdx.x] +
                              redS[2][threadIdx.x] + redS[3][threadIdx.x]) * INVFS[threadIdx.x];
    __syncthreads();

    // Horner: c_j = eval(mc at a_j), r_i = eval(pc at x_i) -> w1, w2
    ull w1[2], w2[2];
    {
        float mcR[KT], pcR[KT];
        #pragma unroll
        for (int k = 0; k < KT; k++) { mcR[k] = coefA[k]; pcR[k] = coefA[16 + k]; }
        ull sc[2], sr[2];
        ull tm = pk2(mcR[KT-1], mcR[KT-1]), tp = pk2(pcR[KT-1], pcR[KT-1]);
        sc[0] = tm; sc[1] = tm; sr[0] = tp; sr[1] = tp;
        #pragma unroll
        for (int k = KT - 2; k >= 0; k--) {
            ull cm = pk2(mcR[k], mcR[k]), cp = pk2(pcR[k], pcR[k]);
            #pragma unroll
            for (int q = 0; q < 2; q++) {
                sc[q] = fma2(sc[q], a2[q], cm);
                sr[q] = fma2(sr[q], x2[q], cp);
            }
        }
        #pragma unroll
        for (int q = 0; q < 2; q++) {
            float clo, chi, rlo, rhi, alo, ahi, xlo, xhi;
            upk2(sc[q], clo, chi); upk2(a2[q], alo, ahi);
            upk2(sr[q], rlo, rhi); upk2(x2[q], xlo, xhi);
            w1[q] = pk2(__fdividef(alo, clo), __fdividef(ahi, chi));
            w2[q] = pk2(__fdividef(xlo, rlo), __fdividef(xhi, rhi));
        }
    }

    // ===== phase B: u_k = sum w1 a^k, v_k = sum w2 x^k =====
    {
        ull svu[2] = {w1[0], w1[1]}, svv[2] = {w2[0], w2[1]};
        #pragma unroll
        for (int ch = 0; ch < 2; ch++) {
            ull uA[7], vA[7];
            #pragma unroll
            for (int k = 0; k < 7; k++) { uA[k] = 0ull; vA[k] = 0ull; }
            #pragma unroll
            for (int q = 0; q < 2; q++) {
                ull pwu = svu[q], pwv = svv[q];
                #pragma unroll
                for (int k = 0; k < 7; k++) {
                    uA[k] = add2(uA[k], pwu); pwu = mul2(pwu, a2[q]);
                    vA[k] = add2(vA[k], pwv); pwv = mul2(pwv, x2[q]);
                }
                svu[q] = pwu; svv[q] = pwv;
            }
            #pragma unroll
            for (int k = 0; k < 7; k++) {
                float lo, hi;
                upk2(uA[k], lo, hi); v[ch * 7 + k]      = lo + hi;
                upk2(vA[k], lo, hi); v[16 + ch * 7 + k] = lo + hi;
            }
        }
        v[14] = 0.f; v[15] = 0.f; v[30] = 0.f; v[31] = 0.f;
    }
    #pragma unroll
    for (int o = 16; o >= 1; o >>= 1) {
        const bool up = (lane & o);
        #pragma unroll
        for (int i = 0; i < o; i++) {
            float send = up ? v[i] : v[i + o];
            float got  = __shfl_xor_sync(0xffffffffu, send, o);
            v[i] = (up ? v[i + o] : v[i]) + got;
        }
    }
    redS[wid][lane] = v[0];
    __syncthreads();
    if (threadIdx.x < 32)
        coefB[threadIdx.x] = (redS[0][threadIdx.x] + redS[1][threadIdx.x] +
                              redS[2][threadIdx.x] + redS[3][threadIdx.x]) * INVFS[threadIdx.x];
    __syncthreads();

    // Horner: C_img = eval(uc at x), C_audio = eval(vc at a); store
    {
        float ucR[KT], vcR[KT];
        #pragma unroll
        for (int k = 0; k < KT; k++) { ucR[k] = coefB[k]; vcR[k] = coefB[16 + k]; }
        ull si[2], so[2];
        ull tu = pk2(ucR[KT-1], ucR[KT-1]), tv = pk2(vcR[KT-1], vcR[KT-1]);
        si[0] = tu; si[1] = tu; so[0] = tv; so[1] = tv;
        #pragma unroll
        for (int k = KT - 2; k >= 0; k--) {
            ull cu = pk2(ucR[k], ucR[k]), cv = pk2(vcR[k], vcR[k]);
            #pragma unroll
            for (int q = 0; q < 2; q++) {
                si[q] = fma2(si[q], x2[q], cu);
                so[q] = fma2(so[q], a2[q], cv);
            }
        }
        ulonglong2 vi; vi.x = si[0]; vi.y = si[1];
        ulonglong2 vo; vo.x = so[0]; vo.y = so[1];
        *(ulonglong2*)&orow[2 * DD + idx] = vi;
        *(ulonglong2*)&orow[3 * DD + idx] = vo;
    }
}

extern "C" void kernel_launch(void* const* d_in, const int* in_sizes, int n_in,
                              void* d_out, int out_size)
{
    const float* img   = (const float*)d_in[0];
    const float* audio = (const float*)d_in[1];
    const float* W     = (const float*)d_in[2];
    const float* bias  = (const float*)d_in[3];
    float* out = (float*)d_out;

    gemm_part_kernel<<<dim3(8, 16, 2), 128>>>(img, W);
    coatten_kernel<<<512, 128>>>(img, audio, bias, out);
}

// round 9
// speedup vs baseline: 1.2684x; 1.0821x over previous
#include <cuda_runtime.h>

#define DD 512
#define BB 512
#define KT 14

// img_t = tanh(img @ W^T + b)
__device__ float g_x[BB * DD];

// inverse factorials by butterfly SLOT: [0..13]=mc/uc, [16..29]=pc/vc
__constant__ float INVFS[32] = {
    1.0f, 1.0f, 0.5f,
    1.6666666666666666e-1f, 4.1666666666666664e-2f, 8.3333333333333333e-3f,
    1.3888888888888889e-3f, 1.9841269841269841e-4f, 2.4801587301587302e-5f,
    2.7557319223985893e-6f, 2.7557319223985888e-7f, 2.5052108385441720e-8f,
    2.0876756987868100e-9f, 1.6059043836821613e-10f,
    0.0f, 0.0f,
    1.0f, 1.0f, 0.5f,
    1.6666666666666666e-1f, 4.1666666666666664e-2f, 8.3333333333333333e-3f,
    1.3888888888888889e-3f, 1.9841269841269841e-4f, 2.4801587301587302e-5f,
    2.7557319223985893e-6f, 2.7557319223985888e-7f, 2.5052108385441720e-8f,
    2.0876756987868100e-9f, 1.6059043836821613e-10f,
    0.0f, 0.0f
};

typedef unsigned long long ull;

__device__ __forceinline__ ull pk2(float lo, float hi) {
    ull r; asm("mov.b64 %0, {%1,%2};" : "=l"(r) : "f"(lo), "f"(hi)); return r;
}
__device__ __forceinline__ void upk2(ull v, float& lo, float& hi) {
    asm("mov.b64 {%0,%1}, %2;" : "=f"(lo), "=f"(hi) : "l"(v));
}
__device__ __forceinline__ ull fma2(ull a, ull b, ull c) {
    ull d; asm("fma.rn.f32x2 %0, %1, %2, %3;" : "=l"(d) : "l"(a), "l"(b), "l"(c));
    return d;
}
__device__ __forceinline__ ull add2(ull a, ull b) {
    ull d; asm("add.rn.f32x2 %0, %1, %2;" : "=l"(d) : "l"(a), "l"(b)); return d;
}
__device__ __forceinline__ ull mul2(ull a, ull b) {
    ull d; asm("mul.rn.f32x2 %0, %1, %2;" : "=l"(d) : "l"(a), "l"(b)); return d;
}

// ---------------------------------------------------------------------------
// Kernel 1: g_x = tanh(img @ W^T + b) — EXACT R3 version (best measured).
// f32x2 SIMT GEMM, 32x64 tile, BK=32, 128 threads, 4x4 microtile, reg prefetch,
// single smem buffer. Grid (8,16) = 128 CTAs.
// ---------------------------------------------------------------------------
__global__ __launch_bounds__(128) void gemm_tanh_kernel(
    const float* __restrict__ A,
    const float* __restrict__ W,
    const float* __restrict__ bias)
{
    __shared__ __align__(16) float Asm[32][36];
    __shared__ __align__(16) float Bsm[32][68];

    const int t  = threadIdx.x;
    const int tx = t & 15;
    const int ty = t >> 4;
    const int rowBase = blockIdx.y * 32;
    const int colBase = blockIdx.x * 64;

    ull acc[2][4];
    #pragma unroll
    for (int p = 0; p < 2; p++)
        #pragma unroll
        for (int n = 0; n < 4; n++) acc[p][n] = 0ull;

    float4 pfA[2], pfB[4];
    #pragma unroll
    for (int rep = 0; rep < 2; rep++) {
        int li = t + rep * 128, r = li >> 3, kq = (li & 7) * 4;
        pfA[rep] = *(const float4*)&A[(rowBase + r) * DD + kq];
    }
    #pragma unroll
    for (int rep = 0; rep < 4; rep++) {
        int li = t + rep * 128, n = li >> 3, kq = (li & 7) * 4;
        pfB[rep] = *(const float4*)&W[(colBase + n) * DD + kq];
    }

    for (int tile = 0; tile < 16; tile++) {
        #pragma unroll
        for (int rep = 0; rep < 2; rep++) {
            int li = t + rep * 128, r = li >> 3, kq = (li & 7) * 4;
            Asm[kq + 0][r] = pfA[rep].x; Asm[kq + 1][r] = pfA[rep].y;
            Asm[kq + 2][r] = pfA[rep].z; Asm[kq + 3][r] = pfA[rep].w;
        }
        #pragma unroll
        for (int rep = 0; rep < 4; rep++) {
            int li = t + rep * 128, n = li >> 3, kq = (li & 7) * 4;
            Bsm[kq + 0][n] = pfB[rep].x; Bsm[kq + 1][n] = pfB[rep].y;
            Bsm[kq + 2][n] = pfB[rep].z; Bsm[kq + 3][n] = pfB[rep].w;
        }
        __syncthreads();

        if (tile < 15) {
            const int kc = (tile + 1) * 32;
            #pragma unroll
            for (int rep = 0; rep < 2; rep++) {
                int li = t + rep * 128, r = li >> 3, kq = (li & 7) * 4;
                pfA[rep] = *(const float4*)&A[(rowBase + r) * DD + kc + kq];
            }
            #pragma unroll
            for (int rep = 0; rep < 4; rep++) {
                int li = t + rep * 128, n = li >> 3, kq = (li & 7) * 4;
                pfB[rep] = *(const float4*)&W[(colBase + n) * DD + kc + kq];
            }
        }

        #pragma unroll
        for (int kk = 0; kk < 32; kk++) {
            ulonglong2 aa = *(const ulonglong2*)&Asm[kk][ty * 4];
            float4 bv = *(const float4*)&Bsm[kk][tx * 4];
            ull b0 = pk2(bv.x, bv.x), b1 = pk2(bv.y, bv.y);
            ull b2 = pk2(bv.z, bv.z), b3 = pk2(bv.w, bv.w);
            acc[0][0] = fma2(aa.x, b0, acc[0][0]);
            acc[0][1] = fma2(aa.x, b1, acc[0][1]);
            acc[0][2] = fma2(aa.x, b2, acc[0][2]);
            acc[0][3] = fma2(aa.x, b3, acc[0][3]);
            acc[1][0] = fma2(aa.y, b0, acc[1][0]);
            acc[1][1] = fma2(aa.y, b1, acc[1][1]);
            acc[1][2] = fma2(aa.y, b2, acc[1][2]);
            acc[1][3] = fma2(aa.y, b3, acc[1][3]);
        }
        __syncthreads();
    }

    float4 bl = *(const float4*)&bias[colBase + tx * 4];
    #pragma unroll
    for (int p = 0; p < 2; p++) {
        float r0[4], r1[4];
        #pragma unroll
        for (int n = 0; n < 4; n++) upk2(acc[p][n], r0[n], r1[n]);
        float4 o0, o1;
        o0.x = tanhf(r0[0] + bl.x); o0.y = tanhf(r0[1] + bl.y);
        o0.z = tanhf(r0[2] + bl.z); o0.w = tanhf(r0[3] + bl.w);
        o1.x = tanhf(r1[0] + bl.x); o1.y = tanhf(r1[1] + bl.y);
        o1.z = tanhf(r1[2] + bl.z); o1.w = tanhf(r1[3] + bl.w);
        int row0 = rowBase + ty * 4 + 2 * p;
        *(float4*)&g_x[row0 * DD + colBase + tx * 4]       = o0;
        *(float4*)&g_x[(row0 + 1) * DD + colBase + tx * 4] = o1;
    }
}

// ---------------------------------------------------------------------------
// Kernel 2: co-attention — R8 version (7.7us measured), reading g_x.
// 1 row/block, 128 thr (4 warps x 128-elem quarter), grid 512.
// Scatter-butterfly reduction (31 shfl) -> lane L owns slot L -> smem combine.
// ---------------------------------------------------------------------------
__global__ __launch_bounds__(128, 1) void coatten_kernel(
    const float* __restrict__ img,
    const float* __restrict__ audio,
    float* __restrict__ out)
{
    const int wid  = threadIdx.x >> 5;
    const int lane = threadIdx.x & 31;
    const int b    = blockIdx.x;
    const int idx  = wid * 128 + 4 * lane;

    __shared__ float redS[4][33];
    __shared__ float coefA[32];
    __shared__ float coefB[32];

    const float* xrow = g_x   + (size_t)b * DD;
    const float* arow = audio + (size_t)b * DD;
    const float* irow = img   + (size_t)b * DD;
    float* orow = out + (size_t)b * (4 * DD);

    ull x2[2], a2[2];
    {
        ulonglong2 xv = *(const ulonglong2*)&xrow[idx];
        ulonglong2 av = *(const ulonglong2*)&arow[idx];
        x2[0] = xv.x; x2[1] = xv.y;
        a2[0] = av.x; a2[1] = av.y;
        *(ulonglong2*)&orow[idx]      = *(const ulonglong2*)&irow[idx];
        *(ulonglong2*)&orow[DD + idx] = av;
    }

    const ull ONE2 = 0x3F8000003F800000ull;
    float v[32];

    // ===== phase A: partial moments m_k = sum x^k, p_k = sum a^k =====
    {
        ull svx[2] = {ONE2, ONE2}, sva[2] = {ONE2, ONE2};
        #pragma unroll
        for (int ch = 0; ch < 2; ch++) {
            ull mA[7], pA[7];
            #pragma unroll
            for (int k = 0; k < 7; k++) { mA[k] = 0ull; pA[k] = 0ull; }
            #pragma unroll
            for (int q = 0; q < 2; q++) {
                ull pwx = svx[q], pwa = sva[q];
                #pragma unroll
                for (int k = 0; k < 7; k++) {
                    mA[k] = add2(mA[k], pwx); pwx = mul2(pwx, x2[q]);
                    pA[k] = add2(pA[k], pwa); pwa = mul2(pwa, a2[q]);
                }
                svx[q] = pwx; sva[q] = pwa;
            }
            #pragma unroll
            for (int k = 0; k < 7; k++) {
                float lo, hi;
                upk2(mA[k], lo, hi); v[ch * 7 + k]      = lo + hi;
                upk2(pA[k], lo, hi); v[16 + ch * 7 + k] = lo + hi;
            }
        }
        v[14] = 0.f; v[15] = 0.f; v[30] = 0.f; v[31] = 0.f;
    }
    // scatter-butterfly: lane L ends owning slot L in v[0]
    #pragma unroll
    for (int o = 16; o >= 1; o >>= 1) {
        const bool up = (lane & o);
        #pragma unroll
        for (int i = 0; i < o; i++) {
            float send = up ? v[i] : v[i + o];
            float got  = __shfl_xor_sync(0xffffffffu, send, o);
            v[i] = (up ? v[i + o] : v[i]) + got;
        }
    }
    redS[wid][lane] = v[0];
    __syncthreads();
    if (threadIdx.x < 32)
        coefA[threadIdx.x] = (redS[0][threadIdx.x] + redS[1][threadIdx.x] +
                              redS[2][threadIdx.x] + redS[3][threadIdx.x]) * INVFS[threadIdx.x];
    __syncthreads();

    // Horner: c_j = eval(mc at a_j), r_i = eval(pc at x_i) -> w1, w2
    ull w1[2], w2[2];
    {
        float mcR[KT], pcR[KT];
        #pragma unroll
        for (int k = 0; k < KT; k++) { mcR[k] = coefA[k]; pcR[k] = coefA[16 + k]; }
        ull sc[2], sr[2];
        ull tm = pk2(mcR[KT-1], mcR[KT-1]), tp = pk2(pcR[KT-1], pcR[KT-1]);
        sc[0] = tm; sc[1] = tm; sr[0] = tp; sr[1] = tp;
        #pragma unroll
        for (int k = KT - 2; k >= 0; k--) {
            ull cm = pk2(mcR[k], mcR[k]), cp = pk2(pcR[k], pcR[k]);
            #pragma unroll
            for (int q = 0; q < 2; q++) {
                sc[q] = fma2(sc[q], a2[q], cm);
                sr[q] = fma2(sr[q], x2[q], cp);
            }
        }
        #pragma unroll
        for (int q = 0; q < 2; q++) {
            float clo, chi, rlo, rhi, alo, ahi, xlo, xhi;
            upk2(sc[q], clo, chi); upk2(a2[q], alo, ahi);
            upk2(sr[q], rlo, rhi); upk2(x2[q], xlo, xhi);
            w1[q] = pk2(__fdividef(alo, clo), __fdividef(ahi, chi));
            w2[q] = pk2(__fdividef(xlo, rlo), __fdividef(xhi, rhi));
        }
    }

    // ===== phase B: u_k = sum w1 a^k, v_k = sum w2 x^k =====
    {
        ull svu[2] = {w1[0], w1[1]}, svv[2] = {w2[0], w2[1]};
        #pragma unroll
        for (int ch = 0; ch < 2; ch++) {
            ull uA[7], vA[7];
            #pragma unroll
            for (int k = 0; k < 7; k++) { uA[k] = 0ull; vA[k] = 0ull; }
            #pragma unroll
            for (int q = 0; q < 2; q++) {
                ull pwu = svu[q], pwv = svv[q];
                #pragma unroll
                for (int k = 0; k < 7; k++) {
                    uA[k] = add2(uA[k], pwu); pwu = mul2(pwu, a2[q]);
                    vA[k] = add2(vA[k], pwv); pwv = mul2(pwv, x2[q]);
                }
                svu[q] = pwu; svv[q] = pwv;
            }
            #pragma unroll
            for (int k = 0; k < 7; k++) {
                float lo, hi;
                upk2(uA[k], lo, hi); v[ch * 7 + k]      = lo + hi;
                upk2(vA[k], lo, hi); v[16 + ch * 7 + k] = lo + hi;
            }
        }
        v[14] = 0.f; v[15] = 0.f; v[30] = 0.f; v[31] = 0.f;
    }
    #pragma unroll
    for (int o = 16; o >= 1; o >>= 1) {
        const bool up = (lane & o);
        #pragma unroll
        for (int i = 0; i < o; i++) {
            float send = up ? v[i] : v[i + o];
            float got  = __shfl_xor_sync(0xffffffffu, send, o);
            v[i] = (up ? v[i + o] : v[i]) + got;
        }
    }
    redS[wid][lane] = v[0];
    __syncthreads();
    if (threadIdx.x < 32)
        coefB[threadIdx.x] = (redS[0][threadIdx.x] + redS[1][threadIdx.x] +
                              redS[2][threadIdx.x] + redS[3][threadIdx.x]) * INVFS[threadIdx.x];
    __syncthreads();

    // Horner: C_img = eval(uc at x), C_audio = eval(vc at a); store
    {
        float ucR[KT], vcR[KT];
        #pragma unroll
        for (int k = 0; k < KT; k++) { ucR[k] = coefB[k]; vcR[k] = coefB[16 + k]; }
        ull si[2], so[2];
        ull tu = pk2(ucR[KT-1], ucR[KT-1]), tv = pk2(vcR[KT-1], vcR[KT-1]);
        si[0] = tu; si[1] = tu; so[0] = tv; so[1] = tv;
        #pragma unroll
        for (int k = KT - 2; k >= 0; k--) {
            ull cu = pk2(ucR[k], ucR[k]), cv = pk2(vcR[k], vcR[k]);
            #pragma unroll
            for (int q = 0; q < 2; q++) {
                si[q] = fma2(si[q], x2[q], cu);
                so[q] = fma2(so[q], a2[q], cv);
            }
        }
        ulonglong2 vi; vi.x = si[0]; vi.y = si[1];
        ulonglong2 vo; vo.x = so[0]; vo.y = so[1];
        *(ulonglong2*)&orow[2 * DD + idx] = vi;
        *(ulonglong2*)&orow[3 * DD + idx] = vo;
    }
}

extern "C" void kernel_launch(void* const* d_in, const int* in_sizes, int n_in,
                              void* d_out, int out_size)
{
    const float* img   = (const float*)d_in[0];
    const float* audio = (const float*)d_in[1];
    const float* W     = (const float*)d_in[2];
    const float* bias  = (const float*)d_in[3];
    float* out = (float*)d_out;

    gemm_tanh_kernel<<<dim3(8, 16), 128>>>(img, W, bias);
    coatten_kernel<<<512, 128>>>(img, audio, out);
}

// round 12
// speedup vs baseline: 1.7079x; 1.3464x over previous
#include <cstdint>
#include <cuda.h>
#include <cuda_runtime.h>
#include <cuda_bf16.h>

#define DD 512
#define BB 512
#define KT 14

// img_t = tanh(img @ W^T + b)
__device__ float g_x[BB * DD];
// bf16 split operands
__device__ __align__(16) __nv_bfloat16 g_Ahi[BB * DD];
__device__ __align__(16) __nv_bfloat16 g_Alo[BB * DD];
__device__ __align__(16) __nv_bfloat16 g_Whi[DD * DD];
__device__ __align__(16) __nv_bfloat16 g_Wlo[DD * DD];

__constant__ float INVFS[32] = {
    1.0f, 1.0f, 0.5f,
    1.6666666666666666e-1f, 4.1666666666666664e-2f, 8.3333333333333333e-3f,
    1.3888888888888889e-3f, 1.9841269841269841e-4f, 2.4801587301587302e-5f,
    2.7557319223985893e-6f, 2.7557319223985888e-7f, 2.5052108385441720e-8f,
    2.0876756987868100e-9f, 1.6059043836821613e-10f,
    0.0f, 0.0f,
    1.0f, 1.0f, 0.5f,
    1.6666666666666666e-1f, 4.1666666666666664e-2f, 8.3333333333333333e-3f,
    1.3888888888888889e-3f, 1.9841269841269841e-4f, 2.4801587301587302e-5f,
    2.7557319223985893e-6f, 2.7557319223985888e-7f, 2.5052108385441720e-8f,
    2.0876756987868100e-9f, 1.6059043836821613e-10f,
    0.0f, 0.0f
};

typedef unsigned long long ull;

__device__ __forceinline__ ull pk2(float lo, float hi) {
    ull r; asm("mov.b64 %0, {%1,%2};" : "=l"(r) : "f"(lo), "f"(hi)); return r;
}
__device__ __forceinline__ void upk2(ull v, float& lo, float& hi) {
    asm("mov.b64 {%0,%1}, %2;" : "=f"(lo), "=f"(hi) : "l"(v));
}
__device__ __forceinline__ ull fma2(ull a, ull b, ull c) {
    ull d; asm("fma.rn.f32x2 %0, %1, %2, %3;" : "=l"(d) : "l"(a), "l"(b), "l"(c));
    return d;
}
__device__ __forceinline__ ull add2(ull a, ull b) {
    ull d; asm("add.rn.f32x2 %0, %1, %2;" : "=l"(d) : "l"(a), "l"(b)); return d;
}
__device__ __forceinline__ ull mul2(ull a, ull b) {
    ull d; asm("mul.rn.f32x2 %0, %1, %2;" : "=l"(d) : "l"(a), "l"(b)); return d;
}

__device__ __forceinline__ void mma16816(float* c,
    uint32_t a0, uint32_t a1, uint32_t a2, uint32_t a3,
    uint32_t b0, uint32_t b1)
{
    asm volatile(
        "mma.sync.aligned.m16n8k16.row.col.f32.bf16.bf16.f32 "
        "{%0,%1,%2,%3}, {%4,%5,%6,%7}, {%8,%9}, {%0,%1,%2,%3};"
        : "+f"(c[0]), "+f"(c[1]), "+f"(c[2]), "+f"(c[3])
        : "r"(a0), "r"(a1), "r"(a2), "r"(a3), "r"(b0), "r"(b1));
}

// ---------------------------------------------------------------------------
// Kernel 0: split fp32 -> bf16 hi/lo for A (img) and W.
// ---------------------------------------------------------------------------
__global__ __launch_bounds__(256) void convert_kernel(
    const float* __restrict__ A, const float* __restrict__ Wm)
{
    const int i = blockIdx.x * 256 + threadIdx.x;   // 0..65535
    float4 va = ((const float4*)A)[i];
    float4 vw = ((const float4*)Wm)[i];

    __nv_bfloat16 h[4], l[4];
    float f[4] = {va.x, va.y, va.z, va.w};
    #pragma unroll
    for (int j = 0; j < 4; j++) {
        h[j] = __float2bfloat16(f[j]);
        l[j] = __float2bfloat16(f[j] - __bfloat162float(h[j]));
    }
    ((__nv_bfloat162*)g_Ahi)[2*i]   = __nv_bfloat162(h[0], h[1]);
    ((__nv_bfloat162*)g_Ahi)[2*i+1] = __nv_bfloat162(h[2], h[3]);
    ((__nv_bfloat162*)g_Alo)[2*i]   = __nv_bfloat162(l[0], l[1]);
    ((__nv_bfloat162*)g_Alo)[2*i+1] = __nv_bfloat162(l[2], l[3]);

    float g[4] = {vw.x, vw.y, vw.z, vw.w};
    #pragma unroll
    for (int j = 0; j < 4; j++) {
        h[j] = __float2bfloat16(g[j]);
        l[j] = __float2bfloat16(g[j] - __bfloat162float(h[j]));
    }
    ((__nv_bfloat162*)g_Whi)[2*i]   = __nv_bfloat162(h[0], h[1]);
    ((__nv_bfloat162*)g_Whi)[2*i+1] = __nv_bfloat162(h[2], h[3]);
    ((__nv_bfloat162*)g_Wlo)[2*i]   = __nv_bfloat162(l[0], l[1]);
    ((__nv_bfloat162*)g_Wlo)[2*i+1] = __nv_bfloat162(l[2], l[3]);
}

// ---------------------------------------------------------------------------
// Kernel 1: split-bf16 GEMM via mma.sync (HMMA) + bias + tanh -> g_x.
// CTA = 64(M) x 32(N), 4 warps (warp = 16 M-rows x 32 N), K-chunks of 64.
// Fragments via direct LDS.32 (bank-conflict-free with pitch 72 bf16).
// 3 streams: hi*hi + hi*lo + lo*hi into fp32 accumulators.
// Grid (16 N-tiles, 8 M-tiles) = 128 CTAs, 128 thr.
// ---------------------------------------------------------------------------
#define PITCH 72   // bf16 units per smem row (36 words -> conflict-free frags)

__global__ __launch_bounds__(128) void gemm_mma_kernel(
    const float* __restrict__ bias)
{
    __shared__ __align__(16) __nv_bfloat16 sAhi[64 * PITCH];
    __shared__ __align__(16) __nv_bfloat16 sAlo[64 * PITCH];
    __shared__ __align__(16) __nv_bfloat16 sBhi[32 * PITCH];
    __shared__ __align__(16) __nv_bfloat16 sBlo[32 * PITCH];

    const int t    = threadIdx.x;
    const int w    = t >> 5;
    const int lane = t & 31;
    const int lq   = lane >> 2;   // lane/4
    const int lr   = lane & 3;    // lane%4
    const int rowBase = blockIdx.y * 64;
    const int colBase = blockIdx.x * 32;

    float acc[4][4];
    #pragma unroll
    for (int nb = 0; nb < 4; nb++)
        #pragma unroll
        for (int c = 0; c < 4; c++) acc[nb][c] = 0.f;

    // loaders: A rows 0..63 (i>>3), 8 uint4/row (i&7); B rows 0..31
    uint4 pAh[4], pAl[4], pBh[2], pBl[2];
    #pragma unroll
    for (int rep = 0; rep < 4; rep++) {
        const int i = t + rep * 128, r = i >> 3, j = i & 7;
        const int ge = (rowBase + r) * DD + j * 8;
        pAh[rep] = *(const uint4*)&g_Ahi[ge];
        pAl[rep] = *(const uint4*)&g_Alo[ge];
    }
    #pragma unroll
    for (int rep = 0; rep < 2; rep++) {
        const int i = t + rep * 128, r = i >> 3, j = i & 7;
        const int ge = (colBase + r) * DD + j * 8;
        pBh[rep] = *(const uint4*)&g_Whi[ge];
        pBl[rep] = *(const uint4*)&g_Wlo[ge];
    }

    const uint32_t* A32h = (const uint32_t*)sAhi;
    const uint32_t* A32l = (const uint32_t*)sAlo;
    const uint32_t* B32h = (const uint32_t*)sBhi;
    const uint32_t* B32l = (const uint32_t*)sBlo;

    for (int chunk = 0; chunk < 8; chunk++) {
        // store prefetched chunk
        #pragma unroll
        for (int rep = 0; rep < 4; rep++) {
            const int i = t + rep * 128, r = i >> 3, j = i & 7;
            *(uint4*)&sAhi[r * PITCH + j * 8] = pAh[rep];
            *(uint4*)&sAlo[r * PITCH + j * 8] = pAl[rep];
        }
        #pragma unroll
        for (int rep = 0; rep < 2; rep++) {
            const int i = t + rep * 128, r = i >> 3, j = i & 7;
            *(uint4*)&sBhi[r * PITCH + j * 8] = pBh[rep];
            *(uint4*)&sBlo[r * PITCH + j * 8] = pBl[rep];
        }
        __syncthreads();

        if (chunk < 7) {
            const int kc = (chunk + 1) * 64;
            #pragma unroll
            for (int rep = 0; rep < 4; rep++) {
                const int i = t + rep * 128, r = i >> 3, j = i & 7;
                const int ge = (rowBase + r) * DD + kc + j * 8;
                pAh[rep] = *(const uint4*)&g_Ahi[ge];
                pAl[rep] = *(const uint4*)&g_Alo[ge];
            }
            #pragma unroll
            for (int rep = 0; rep < 2; rep++) {
                const int i = t + rep * 128, r = i >> 3, j = i & 7;
                const int ge = (colBase + r) * DD + kc + j * 8;
                pBh[rep] = *(const uint4*)&g_Whi[ge];
                pBl[rep] = *(const uint4*)&g_Wlo[ge];
            }
        }

        // compute: 4 k-steps of 16
        #pragma unroll
        for (int ks = 0; ks < 4; ks++) {
            const int kw = ks * 8;  // k0/2 in words
            const int ab = (w * 16 + lq) * (PITCH / 2) + kw + lr;
            const uint32_t a0h = A32h[ab];
            const uint32_t a1h = A32h[ab + 8 * (PITCH / 2)];
            const uint32_t a2h = A32h[ab + 4];
            const uint32_t a3h = A32h[ab + 8 * (PITCH / 2) + 4];
            const uint32_t a0l = A32l[ab];
            const uint32_t a1l = A32l[ab + 8 * (PITCH / 2)];
            const uint32_t a2l = A32l[ab + 4];
            const uint32_t a3l = A32l[ab + 8 * (PITCH / 2) + 4];
            #pragma unroll
            for (int nb = 0; nb < 4; nb++) {
                const int bb = (nb * 8 + lq) * (PITCH / 2) + kw + lr;
                const uint32_t b0h = B32h[bb], b1h = B32h[bb + 4];
                const uint32_t b0l = B32l[bb], b1l = B32l[bb + 4];
                mma16816(acc[nb], a0h, a1h, a2h, a3h, b0h, b1h);
                mma16816(acc[nb], a0h, a1h, a2h, a3h, b0l, b1l);
                mma16816(acc[nb], a0l, a1l, a2l, a3l, b0h, b1h);
            }
        }
        __syncthreads();
    }

    // epilogue: bias + tanh -> g_x
    const int row0 = rowBase + w * 16 + lq;
    const int row1 = row0 + 8;
    #pragma unroll
    for (int nb = 0; nb < 4; nb++) {
        const int col = colBase + nb * 8 + lr * 2;
        const float b0 = bias[col], b1 = bias[col + 1];
        float2 o0, o1;
        o0.x = tanhf(acc[nb][0] + b0); o0.y = tanhf(acc[nb][1] + b1);
        o1.x = tanhf(acc[nb][2] + b0); o1.y = tanhf(acc[nb][3] + b1);
        *(float2*)&g_x[row0 * DD + col] = o0;
        *(float2*)&g_x[row1 * DD + col] = o1;
    }
}

// ---------------------------------------------------------------------------
// Kernel 2: co-attention — unchanged R9 (7.1us measured).
// ---------------------------------------------------------------------------
__global__ __launch_bounds__(128, 1) void coatten_kernel(
    const float* __restrict__ img,
    const float* __restrict__ audio,
    float* __restrict__ out)
{
    const int wid  = threadIdx.x >> 5;
    const int lane = threadIdx.x & 31;
    const int b    = blockIdx.x;
    const int idx  = wid * 128 + 4 * lane;

    __shared__ float redS[4][33];
    __shared__ float coefA[32];
    __shared__ float coefB[32];

    const float* xrow = g_x   + (size_t)b * DD;
    const float* arow = audio + (size_t)b * DD;
    const float* irow = img   + (size_t)b * DD;
    float* orow = out + (size_t)b * (4 * DD);

    ull x2[2], a2[2];
    {
        ulonglong2 xv = *(const ulonglong2*)&xrow[idx];
        ulonglong2 av = *(const ulonglong2*)&arow[idx];
        x2[0] = xv.x; x2[1] = xv.y;
        a2[0] = av.x; a2[1] = av.y;
        *(ulonglong2*)&orow[idx]      = *(const ulonglong2*)&irow[idx];
        *(ulonglong2*)&orow[DD + idx] = av;
    }

    const ull ONE2 = 0x3F8000003F800000ull;
    float v[32];

    {
        ull svx[2] = {ONE2, ONE2}, sva[2] = {ONE2, ONE2};
        #pragma unroll
        for (int ch = 0; ch < 2; ch++) {
            ull mA[7], pA[7];
            #pragma unroll
            for (int k = 0; k < 7; k++) { mA[k] = 0ull; pA[k] = 0ull; }
            #pragma unroll
            for (int q = 0; q < 2; q++) {
                ull pwx = svx[q], pwa = sva[q];
                #pragma unroll
                for (int k = 0; k < 7; k++) {
                    mA[k] = add2(mA[k], pwx); pwx = mul2(pwx, x2[q]);
                    pA[k] = add2(pA[k], pwa); pwa = mul2(pwa, a2[q]);
                }
                svx[q] = pwx; sva[q] = pwa;
            }
            #pragma unroll
            for (int k = 0; k < 7; k++) {
                float lo, hi;
                upk2(mA[k], lo, hi); v[ch * 7 + k]      = lo + hi;
                upk2(pA[k], lo, hi); v[16 + ch * 7 + k] = lo + hi;
            }
        }
        v[14] = 0.f; v[15] = 0.f; v[30] = 0.f; v[31] = 0.f;
    }
    #pragma unroll
    for (int o = 16; o >= 1; o >>= 1) {
        const bool up = (lane & o);
        #pragma unroll
        for (int i = 0; i < o; i++) {
            float send = up ? v[i] : v[i + o];
            float got  = __shfl_xor_sync(0xffffffffu, send, o);
            v[i] = (up ? v[i + o] : v[i]) + got;
        }
    }
    redS[wid][lane] = v[0];
    __syncthreads();
    if (threadIdx.x < 32)
        coefA[threadIdx.x] = (redS[0][threadIdx.x] + redS[1][threadIdx.x] +
                              redS[2][threadIdx.x] + redS[3][threadIdx.x]) * INVFS[threadIdx.x];
    __syncthreads();

    ull w1[2], w2[2];
    {
        float mcR[KT], pcR[KT];
        #pragma unroll
        for (int k = 0; k < KT; k++) { mcR[k] = coefA[k]; pcR[k] = coefA[16 + k]; }
        ull sc[2], sr[2];
        ull tm = pk2(mcR[KT-1], mcR[KT-1]), tp = pk2(pcR[KT-1], pcR[KT-1]);
        sc[0] = tm; sc[1] = tm; sr[0] = tp; sr[1] = tp;
        #pragma unroll
        for (int k = KT - 2; k >= 0; k--) {
            ull cm = pk2(mcR[k], mcR[k]), cp = pk2(pcR[k], pcR[k]);
            #pragma unroll
            for (int q = 0; q < 2; q++) {
                sc[q] = fma2(sc[q], a2[q], cm);
                sr[q] = fma2(sr[q], x2[q], cp);
            }
        }
        #pragma unroll
        for (int q = 0; q < 2; q++) {
            float clo, chi, rlo, rhi, alo, ahi, xlo, xhi;
            upk2(sc[q], clo, chi); upk2(a2[q], alo, ahi);
            upk2(sr[q], rlo, rhi); upk2(x2[q], xlo, xhi);
            w1[q] = pk2(__fdividef(alo, clo), __fdividef(ahi, chi));
            w2[q] = pk2(__fdividef(xlo, rlo), __fdividef(xhi, rhi));
        }
    }

    {
        ull svu[2] = {w1[0], w1[1]}, svv[2] = {w2[0], w2[1]};
        #pragma unroll
        for (int ch = 0; ch < 2; ch++) {
            ull uA[7], vA[7];
            #pragma unroll
            for (int k = 0; k < 7; k++) { uA[k] = 0ull; vA[k] = 0ull; }
            #pragma unroll
            for (int q = 0; q < 2; q++) {
                ull pwu = svu[q], pwv = svv[q];
                #pragma unroll
                for (int k = 0; k < 7; k++) {
                    uA[k] = add2(uA[k], pwu); pwu = mul2(pwu, a2[q]);
                    vA[k] = add2(vA[k], pwv); pwv = mul2(pwv, x2[q]);
                }
                svu[q] = pwu; svv[q] = pwv;
            }
            #pragma unroll
            for (int k = 0; k < 7; k++) {
                float lo, hi;
                upk2(uA[k], lo, hi); v[ch * 7 + k]      = lo + hi;
                upk2(vA[k], lo, hi); v[16 + ch * 7 + k] = lo + hi;
            }
        }
        v[14] = 0.f; v[15] = 0.f; v[30] = 0.f; v[31] = 0.f;
    }
    #pragma unroll
    for (int o = 16; o >= 1; o >>= 1) {
        const bool up = (lane & o);
        #pragma unroll
        for (int i = 0; i < o; i++) {
            float send = up ? v[i] : v[i + o];
            float got  = __shfl_xor_sync(0xffffffffu, send, o);
            v[i] = (up ? v[i + o] : v[i]) + got;
        }
    }
    redS[wid][lane] = v[0];
    __syncthreads();
    if (threadIdx.x < 32)
        coefB[threadIdx.x] = (redS[0][threadIdx.x] + redS[1][threadIdx.x] +
                              redS[2][threadIdx.x] + redS[3][threadIdx.x]) * INVFS[threadIdx.x];
    __syncthreads();

    {
        float ucR[KT], vcR[KT];
        #pragma unroll
        for (int k = 0; k < KT; k++) { ucR[k] = coefB[k]; vcR[k] = coefB[16 + k]; }
        ull si[2], so[2];
        ull tu = pk2(ucR[KT-1], ucR[KT-1]), tv = pk2(vcR[KT-1], vcR[KT-1]);
        si[0] = tu; si[1] = tu; so[0] = tv; so[1] = tv;
        #pragma unroll
        for (int k = KT - 2; k >= 0; k--) {
            ull cu = pk2(ucR[k], ucR[k]), cv = pk2(vcR[k], vcR[k]);
            #pragma unroll
            for (int q = 0; q < 2; q++) {
                si[q] = fma2(si[q], x2[q], cu);
                so[q] = fma2(so[q], a2[q], cv);
            }
        }
        ulonglong2 vi; vi.x = si[0]; vi.y = si[1];
        ulonglong2 vo; vo.x = so[0]; vo.y = so[1];
        *(ulonglong2*)&orow[2 * DD + idx] = vi;
        *(ulonglong2*)&orow[3 * DD + idx] = vo;
    }
}

extern "C" void kernel_launch(void* const* d_in, const int* in_sizes, int n_in,
                              void* d_out, int out_size)
{
    const float* img   = (const float*)d_in[0];
    const float* audio = (const float*)d_in[1];
    const float* W     = (const float*)d_in[2];
    const float* bias  = (const float*)d_in[3];
    float* out = (float*)d_out;

    convert_kernel<<<256, 256>>>(img, W);
    gemm_mma_kernel<<<dim3(16, 8), 128>>>(bias);
    coatten_kernel<<<512, 128>>>(img, audio, out);
}